// round 7
// baseline (speedup 1.0000x reference)
#include <cuda_runtime.h>
#include <cstdint>

// YOLO loss: persistent cp.async pipelined reduction (R2 structure,
// re-geometried for 16 warps/SM: 128 threads, TILE=128, 2 stages).
// preds:   [802816 x 30] f32 (96.3MB), targets: [802816 x 25] f32 (80.3MB).

#define THREADS 128
#define TILE 128                       // cells per tile (1 per thread)
#define STAGES 2
#define PRED_F4 (TILE * 30 / 4)        // 960 float4 per tile
#define TGT_F4  (TILE * 25 / 4)        // 800 float4 per tile
#define STAGE_FLOATS (TILE * 55)       // 7040 floats = 28160 B per stage
#define SMEM_BYTES (STAGES * STAGE_FLOATS * 4)   // 56320 B -> 4 blocks/SM
#define GRID 592                       // 148 SMs x 4 blocks persistent

#define LAMBDA_COORD 5.0f
#define LAMBDA_NOOBJ 0.5f

__global__ void yolo_zero_kernel(float* out) {
    if (threadIdx.x == 0) out[0] = 0.0f;
}

__device__ __forceinline__ void cp16(uint32_t smem_addr, const float4* gptr) {
    asm volatile("cp.async.cg.shared.global [%0], [%1], 16;"
                 :: "r"(smem_addr), "l"(gptr));
}

__global__ __launch_bounds__(THREADS)
void yolo_loss_kernel(const float* __restrict__ preds,
                      const float* __restrict__ targets,
                      float* __restrict__ out,
                      int ntiles) {
    extern __shared__ float buf[];     // STAGES * STAGE_FLOATS
    __shared__ float wsum[THREADS / 32];

    const int tid = threadIdx.x;
    const int grid = gridDim.x;
    const uint32_t sbase = (uint32_t)__cvta_generic_to_shared(buf);

    // Issue async loads for one tile into one stage; always commit a group
    // (possibly empty) so group counting stays uniform.
    auto issue = [&](int tile, int stage) {
        if (tile < ntiles) {
            const float4* pg = reinterpret_cast<const float4*>(preds)
                               + (size_t)tile * PRED_F4;
            const uint32_t sp = sbase + (uint32_t)stage * (STAGE_FLOATS * 4);
            for (int idx = tid; idx < PRED_F4; idx += THREADS)   // 7.5/thread
                cp16(sp + idx * 16, pg + idx);
            const float4* tg = reinterpret_cast<const float4*>(targets)
                               + (size_t)tile * TGT_F4;
            const uint32_t st = sp + TILE * 30 * 4;
            for (int idx = tid; idx < TGT_F4; idx += THREADS)    // 6.25/thread
                cp16(st + idx * 16, tg + idx);
        }
        asm volatile("cp.async.commit_group;");
    };

    const int t0 = (int)blockIdx.x;

    // Prologue: both stages in flight.
    issue(t0, 0);
    issue(t0 + grid, 1);

    float acc = 0.0f;
    int i = 0;
    for (int t = t0; t < ntiles; t += grid, i++) {
        const int stage = i & 1;

        asm volatile("cp.async.wait_group 1;");   // group i complete
        __syncthreads();

        const float* p  = buf + stage * STAGE_FLOATS + tid * 30;
        const float* tg = buf + stage * STAGE_FLOATS + TILE * 30 + tid * 25;

        const float s0 = p[0];
        const float s1 = p[5];
        const int off = (s1 > s0) ? 5 : 0;   // argmax, first-max tiebreak

        float loss;
        if (tg[0] == 1.0f) {
            float box_loss = 0.0f;
            #pragma unroll
            for (int k = 1; k < 5; k++) {
                const float d = p[off + k] - tg[k];
                box_loss = fmaf(d, d, box_loss);
            }
            const float dpc = p[off] - 1.0f;   // tg[0] == 1 exactly
            float class_loss = 0.0f;
            #pragma unroll
            for (int j = 0; j < 20; j++) {
                const float d = p[10 + j] - tg[5 + j];
                class_loss = fmaf(d, d, class_loss);
            }
            loss = fmaf(LAMBDA_COORD, box_loss, fmaf(dpc, dpc, class_loss));
        } else {
            loss = LAMBDA_NOOBJ * (s0 * s0 + s1 * s1);
        }
        acc += loss;

        __syncthreads();                       // stage free for reuse
        issue(t + 2 * grid, stage);            // refill consumed stage
    }

    asm volatile("cp.async.wait_group 0;");    // drain (empty tails)

    // Block reduce once, single atomic per block (592 total).
    #pragma unroll
    for (int o = 16; o > 0; o >>= 1)
        acc += __shfl_xor_sync(0xffffffffu, acc, o);
    if ((tid & 31) == 0) wsum[tid >> 5] = acc;
    __syncthreads();

    if (tid == 0) {
        float v = wsum[0];
        #pragma unroll
        for (int w = 1; w < THREADS / 32; w++) v += wsum[w];
        atomicAdd(out, v);
    }
}

extern "C" void kernel_launch(void* const* d_in, const int* in_sizes, int n_in,
                              void* d_out, int out_size) {
    const float* preds   = (const float*)d_in[0];
    const float* targets = (const float*)d_in[1];
    float* out = (float*)d_out;

    const int ncells = in_sizes[0] / 30;       // 802816
    const int ntiles = ncells / TILE;          // 6272

    cudaFuncSetAttribute(yolo_loss_kernel,
                         cudaFuncAttributeMaxDynamicSharedMemorySize, SMEM_BYTES);

    yolo_zero_kernel<<<1, 32>>>(out);
    yolo_loss_kernel<<<GRID, THREADS, SMEM_BYTES>>>(preds, targets, out, ntiles);
}

// round 8
// speedup vs baseline: 1.1084x; 1.1084x over previous
#include <cuda_runtime.h>
#include <cstdint>

// YOLO loss: persistent TMA-bulk (cp.async.bulk + mbarrier) 3-stage pipeline.
// preds: [802816 x 30] f32 (96.3MB), targets: [802816 x 25] f32 (80.3MB).
// One elected thread issues 2 bulk copies per stage; per-stage mbarrier
// complete_tx signals readiness. 2 blocks/SM, 112KB/SM in flight.

#define THREADS 128
#define TILE 128                        // cells per tile (1 per thread)
#define STAGES 3
#define PRED_BYTES (TILE * 30 * 4)      // 15360
#define TGT_BYTES  (TILE * 25 * 4)      // 12800
#define STAGE_BYTES (PRED_BYTES + TGT_BYTES)     // 28160
#define SMEM_BYTES (STAGES * STAGE_BYTES)        // 84480 -> 2 blocks/SM
#define GRID 296                        // 148 SMs x 2 blocks persistent

#define LAMBDA_COORD 5.0f
#define LAMBDA_NOOBJ 0.5f

__global__ void yolo_zero_kernel(float* out) {
    if (threadIdx.x == 0) out[0] = 0.0f;
}

__device__ __forceinline__ void mbar_init(uint32_t mbar, uint32_t count) {
    asm volatile("mbarrier.init.shared.b64 [%0], %1;" :: "r"(mbar), "r"(count)
                 : "memory");
}
__device__ __forceinline__ void mbar_expect_tx(uint32_t mbar, uint32_t bytes) {
    asm volatile("mbarrier.arrive.expect_tx.shared.b64 _, [%0], %1;"
                 :: "r"(mbar), "r"(bytes) : "memory");
}
__device__ __forceinline__ void bulk_g2s(uint32_t sdst, const void* gsrc,
                                         uint32_t bytes, uint32_t mbar) {
    asm volatile(
        "cp.async.bulk.shared::cta.global.mbarrier::complete_tx::bytes "
        "[%0], [%1], %2, [%3];"
        :: "r"(sdst), "l"(gsrc), "r"(bytes), "r"(mbar) : "memory");
}
__device__ __forceinline__ void mbar_wait(uint32_t mbar, uint32_t parity) {
    uint32_t done;
    asm volatile(
        "{\n\t.reg .pred p;\n\t"
        "mbarrier.try_wait.parity.acquire.cta.shared::cta.b64 p, [%1], %2;\n\t"
        "selp.b32 %0, 1, 0, p;\n\t}"
        : "=r"(done) : "r"(mbar), "r"(parity) : "memory");
    if (!done) {
        asm volatile(
            "{\n\t.reg .pred P1;\n\t"
            "WL_%=:\n\t"
            "mbarrier.try_wait.parity.acquire.cta.shared::cta.b64 P1, [%0], %1, 0x989680;\n\t"
            "@P1 bra.uni WD_%=;\n\t"
            "bra.uni WL_%=;\n\t"
            "WD_%=:\n\t}"
            :: "r"(mbar), "r"(parity) : "memory");
    }
}

__global__ __launch_bounds__(THREADS)
void yolo_loss_kernel(const float* __restrict__ preds,
                      const float* __restrict__ targets,
                      float* __restrict__ out,
                      int ntiles) {
    extern __shared__ __align__(16) float buf[];   // STAGES * STAGE_BYTES
    __shared__ __align__(8) uint64_t mbar_storage[STAGES];
    __shared__ float wsum[THREADS / 32];

    const int tid = threadIdx.x;
    const int grid = gridDim.x;
    const uint32_t sbase = (uint32_t)__cvta_generic_to_shared(buf);
    const uint32_t mb0 = (uint32_t)__cvta_generic_to_shared(mbar_storage);

    if (tid == 0) {
        #pragma unroll
        for (int s = 0; s < STAGES; s++) mbar_init(mb0 + s * 8, 1);
    }
    __syncthreads();

    // Issue one tile's loads into one stage (elected thread only).
    auto issue = [&](int tile, int stage) {
        if (tile < ntiles && tid == 0) {
            const uint32_t mb = mb0 + stage * 8;
            const uint32_t sp = sbase + (uint32_t)stage * STAGE_BYTES;
            mbar_expect_tx(mb, STAGE_BYTES);
            bulk_g2s(sp, (const char*)preds + (size_t)tile * PRED_BYTES,
                     PRED_BYTES, mb);
            bulk_g2s(sp + PRED_BYTES, (const char*)targets + (size_t)tile * TGT_BYTES,
                     TGT_BYTES, mb);
        }
    };

    const int t0 = (int)blockIdx.x;

    // Prologue: fill all 3 stages.
    issue(t0, 0);
    issue(t0 + grid, 1);
    issue(t0 + 2 * grid, 2);

    float acc = 0.0f;
    int i = 0;
    for (int t = t0; t < ntiles; t += grid, i++) {
        const int stage = i % STAGES;
        const uint32_t parity = (uint32_t)((i / STAGES) & 1);

        mbar_wait(mb0 + stage * 8, parity);    // stage data landed

        const float* p  = buf + stage * (STAGE_BYTES / 4) + tid * 30;
        const float* tg = buf + stage * (STAGE_BYTES / 4) + TILE * 30 + tid * 25;

        const float s0 = p[0];
        const float s1 = p[5];
        const int off = (s1 > s0) ? 5 : 0;     // argmax, first-max tiebreak

        float loss;
        if (tg[0] == 1.0f) {
            float box_loss = 0.0f;
            #pragma unroll
            for (int k = 1; k < 5; k++) {
                const float d = p[off + k] - tg[k];
                box_loss = fmaf(d, d, box_loss);
            }
            const float dpc = p[off] - 1.0f;   // tg[0] == 1 exactly
            float class_loss = 0.0f;
            #pragma unroll
            for (int j = 0; j < 20; j++) {
                const float d = p[10 + j] - tg[5 + j];
                class_loss = fmaf(d, d, class_loss);
            }
            loss = fmaf(LAMBDA_COORD, box_loss, fmaf(dpc, dpc, class_loss));
        } else {
            loss = LAMBDA_NOOBJ * (s0 * s0 + s1 * s1);
        }
        acc += loss;

        __syncthreads();                       // all threads done with stage
        issue(t + STAGES * grid, stage);       // refill consumed stage
    }

    // Every issued copy has been waited on; nothing in flight at exit.

    // Block reduce once, single atomic per block (296 total).
    #pragma unroll
    for (int o = 16; o > 0; o >>= 1)
        acc += __shfl_xor_sync(0xffffffffu, acc, o);
    if ((tid & 31) == 0) wsum[tid >> 5] = acc;
    __syncthreads();

    if (tid == 0) {
        float v = wsum[0];
        #pragma unroll
        for (int w = 1; w < THREADS / 32; w++) v += wsum[w];
        atomicAdd(out, v);
    }
}

extern "C" void kernel_launch(void* const* d_in, const int* in_sizes, int n_in,
                              void* d_out, int out_size) {
    const float* preds   = (const float*)d_in[0];
    const float* targets = (const float*)d_in[1];
    float* out = (float*)d_out;

    const int ncells = in_sizes[0] / 30;       // 802816
    const int ntiles = ncells / TILE;          // 6272

    cudaFuncSetAttribute(yolo_loss_kernel,
                         cudaFuncAttributeMaxDynamicSharedMemorySize, SMEM_BYTES);

    yolo_zero_kernel<<<1, 32>>>(out);
    yolo_loss_kernel<<<GRID, THREADS, SMEM_BYTES>>>(preds, targets, out, ntiles);
}